// round 11
// baseline (speedup 1.0000x reference)
#include <cuda_runtime.h>
#include <cstdint>

#define Bn 16
#define Ln 65536
#define Hn 64
#define Kn 64
#define LOUT (Ln - Hn + 1)              /* 65473 */
#define TILE_M 256
#define NTILES ((LOUT + TILE_M - 1) / TILE_M)   /* 256 */
#define NB_MAIN (NTILES * Bn)                   /* 4096 */
#define THREADS 256                      /* 8 warps, each M=32 x N=64 */

// ---- dynamic SMEM layout (bytes) ----
#define OFF_S     0          /* 64 floats: S_k */
#define OFF_BV    256        /* 64 floats: b_k */
#define OFF_INV   512        /* 256 floats: 1/(sd+eps) */
#define OFF_MUI   1536       /* 256 floats: mu*inv */
#define OFF_XS    2560       /* 328 floats: tf32-rounded x window */
#define OFF_XS2   3872       /* 320 float2: {xs[i], xs[i+4]} pairs */
#define OFF_W     6432       /* 64 rows x 288B = 18432, ends 24864 */
// epilogue staging overlays W/xs (dead after MMA): 8 warps x 4608B
#define OFF_STAGE OFF_W
#define WSTAGE    4608       /* 16 rows * 72 words * 4B per warp */
#define SMEM_BYTES (OFF_STAGE + 8 * WSTAGE)   /* 43296 */

__device__ __forceinline__ float tf32r(float v) {
    uint32_t t;
    asm("cvt.rna.tf32.f32 %0, %1;" : "=r"(t) : "f"(v));
    return __uint_as_float(t);
}

__device__ __forceinline__ void mma_tf32(float* c, const uint32_t* a,
                                         uint32_t b0, uint32_t b1) {
    asm volatile(
        "mma.sync.aligned.m16n8k8.row.col.f32.tf32.tf32.f32 "
        "{%0,%1,%2,%3}, {%4,%5,%6,%7}, {%8,%9}, {%0,%1,%2,%3};"
        : "+f"(c[0]), "+f"(c[1]), "+f"(c[2]), "+f"(c[3])
        : "r"(a[0]), "r"(a[1]), "r"(a[2]), "r"(a[3]), "r"(b0), "r"(b1));
}

__global__ void __launch_bounds__(THREADS, 2)
hankel_filterbank_kernel(const float* __restrict__ x,
                         const float* __restrict__ Wg,
                         const float* __restrict__ bv,
                         float* __restrict__ out,
                         long long expected, int extra)
{
    const int bx = blockIdx.x;
    const int tid = threadIdx.x;

    // ---- tail-fill block: packed tuple remainder, no barriers ----
    if (bx >= NB_MAIN) {
        for (int i = tid; i < extra; i += THREADS)
            out[expected + i] = 63.0f;   // warmup scalar
        return;
    }

    extern __shared__ char sm[];
    const int wid = tid >> 5;
    const int lid = tid & 31;
    const int g   = lid >> 2;     // group id 0..7
    const int ct  = lid & 3;      // thread-in-group
    const int t0  = (bx & (NTILES - 1)) * TILE_M;
    const int batch = bx >> 8;    // NTILES == 256

    float* xs   = (float*)(sm + OFF_XS);
    float2* xs2 = (float2*)(sm + OFF_XS2);

    // ---- stage + tf32-round x window (zero past end) ----
    const float* xb = x + (size_t)batch * Ln;
#pragma unroll
    for (int i = tid; i < 328; i += THREADS) {
        int gi = t0 + i;
        xs[i] = (gi < Ln) ? tf32r(xb[gi]) : 0.0f;
    }

    // ---- W -> permuted tf32 SMEM (288B rows), float4 in / float4 out ----
    // pairs p = kk*4+e at row n: {W~[n][8kk+e], W~[n][8kk+e+4]}
    {
        const float4* Wv = (const float4*)Wg;
#pragma unroll
        for (int j = tid; j < 512; j += THREADS) {
            int n = j >> 3, kk = j & 7;
            float4 a = Wv[n * 16 + 2 * kk];       // cols 8kk..8kk+3
            float4 b = Wv[n * 16 + 2 * kk + 1];   // cols 8kk+4..8kk+7
            float4 p0, p1;
            p0.x = tf32r(a.x); p0.y = tf32r(b.x);
            p0.z = tf32r(a.y); p0.w = tf32r(b.y);
            p1.x = tf32r(a.z); p1.y = tf32r(b.z);
            p1.z = tf32r(a.w); p1.w = tf32r(b.w);
            char* dst = sm + OFF_W + n * 288 + kk * 32;
            *(float4*)dst = p0;
            *(float4*)(dst + 16) = p1;
        }
    }
    if (tid < Kn) ((float*)(sm + OFF_BV))[tid] = bv[tid];
    __syncthreads();

    // ---- S_k from converted SMEM tile (warp w -> rows 8w..8w+7) ----
    {
        // 2 rows per pass: lane reads float4 (l&15) of row 8w + (l>>4)
#pragma unroll
        for (int pass = 0; pass < 4; ++pass) {
            int row = (wid << 3) + (pass << 1) + (lid >> 4);
            float4 v = *(const float4*)(sm + OFF_W + row * 288 + (lid & 15) * 16);
            float s = (v.x + v.y) + (v.z + v.w);
#pragma unroll
            for (int o = 8; o > 0; o >>= 1)
                s += __shfl_xor_sync(0xFFFFFFFFu, s, o);
            if ((lid & 15) == 0) ((float*)(sm + OFF_S))[row] = s;
        }
    }

    // ---- xs2 pairs; per-row stats (row = tid) ----
#pragma unroll
    for (int i = tid; i < 320; i += THREADS) {
        float2 p;
        p.x = xs[i];
        p.y = xs[i + 4];
        xs2[i] = p;
    }
    {
        float sum = 0.0f, sq = 0.0f;
#pragma unroll
        for (int h = 0; h < Hn; ++h) {
            float v = xs[tid + h];
            sum += v;
            sq = fmaf(v, v, sq);
        }
        float mu  = sum * (1.0f / 64.0f);
        float var = fmaxf(sq - sum * mu, 0.0f) * (1.0f / 63.0f);
        float inv = 1.0f / (sqrtf(var) + 1e-6f);
        ((float*)(sm + OFF_INV))[tid] = inv;
        ((float*)(sm + OFF_MUI))[tid] = mu * inv;
    }
    __syncthreads();

    // ---- warp MMA: 32 rows x 64 cols per warp (2 m16 tiles share B) ----
    const int Rw = wid << 5;   // warp row base within tile
    float c[2][8][4];
#pragma unroll
    for (int mb = 0; mb < 2; ++mb)
#pragma unroll
        for (int nb = 0; nb < 8; ++nb)
#pragma unroll
            for (int r = 0; r < 4; ++r) c[mb][nb][r] = 0.0f;

#pragma unroll
    for (int kk = 0; kk < 8; ++kk) {
        const int kc = kk * 8 + ct;
        const int base = Rw + g + kc;
        float2 aA0 = xs2[base];          // rows g      of tile mb0
        float2 aB0 = xs2[base + 8];      // rows g+8
        float2 aA1 = xs2[base + 16];     // rows g      of tile mb1
        float2 aB1 = xs2[base + 24];     // rows g+8
        uint32_t a0[4] = { __float_as_uint(aA0.x), __float_as_uint(aB0.x),
                           __float_as_uint(aA0.y), __float_as_uint(aB0.y) };
        uint32_t a1[4] = { __float_as_uint(aA1.x), __float_as_uint(aB1.x),
                           __float_as_uint(aA1.y), __float_as_uint(aB1.y) };
#pragma unroll
        for (int nb = 0; nb < 8; ++nb) {
            int n = (nb << 3) + g;
            float2 bb = *(const float2*)(sm + OFF_W + n * 288 + (kk * 4 + ct) * 8);
            uint32_t b0 = __float_as_uint(bb.x), b1 = __float_as_uint(bb.y);
            mma_tf32(c[0][nb], a0, b0, b1);
            mma_tf32(c[1][nb], a1, b0, b1);
        }
    }

    __syncthreads();   // W/xs dead; staging region becomes free

    // ---- epilogue: stride-72 staging (bank-clean, no overlap) ----
    const float* Ss  = (const float*)(sm + OFF_S);
    const float* bs  = (const float*)(sm + OFF_BV);
    const float* inv = (const float*)(sm + OFF_INV);
    const float* mui = (const float*)(sm + OFF_MUI);
    float* stw  = (float*)(sm + OFF_STAGE + wid * WSTAGE);
    float* outb = out + (size_t)batch * LOUT * Kn;

#pragma unroll
    for (int mb = 0; mb < 2; ++mb) {
        const int rA = Rw + (mb << 4) + g;
        const float iA = inv[rA],     mA = mui[rA];
        const float iB = inv[rA + 8], mB = mui[rA + 8];
#pragma unroll
        for (int nb = 0; nb < 8; ++nb) {
            int col = (nb << 3) + (ct << 1);
            float2 S2 = *(const float2*)(Ss + col);
            float2 b2 = *(const float2*)(bs + col);
            float2 yA, yB;
            yA.x = fmaxf(fmaf(c[mb][nb][0], iA, fmaf(-mA, S2.x, b2.x)), 0.0f);
            yA.y = fmaxf(fmaf(c[mb][nb][1], iA, fmaf(-mA, S2.y, b2.y)), 0.0f);
            yB.x = fmaxf(fmaf(c[mb][nb][2], iB, fmaf(-mB, S2.x, b2.x)), 0.0f);
            yB.y = fmaxf(fmaf(c[mb][nb][3], iB, fmaf(-mB, S2.y, b2.y)), 0.0f);
            *(float2*)(stw + g * 72 + col)       = yA;   // 16 rows x 64 cols
            *(float2*)(stw + (g + 8) * 72 + col) = yB;   // stride 72: no overlap
        }
        __syncwarp();

        // coalesced streaming stores: lanes 0-15 -> one row's 256B, 16-31 -> next
#pragma unroll
        for (int i = 0; i < 8; ++i) {
            int row  = (i << 1) + (lid >> 4);
            int quad = lid & 15;
            int gr = t0 + Rw + (mb << 4) + row;
            if (gr < LOUT) {
                float4 v = *(const float4*)(stw + row * 72 + (quad << 2));
                __stcs((float4*)(outb + (size_t)gr * Kn + (quad << 2)), v);
            }
        }
        __syncwarp();
    }
}

extern "C" void kernel_launch(void* const* d_in, const int* in_sizes, int n_in,
                              void* d_out, int out_size) {
    const float* x  = (const float*)d_in[0];
    const float* W  = (const float*)d_in[1];
    const float* bv = (const float*)d_in[2];
    float* out = (float*)d_out;

    long long expected = (long long)Bn * LOUT * Kn;
    int extra = ((long long)out_size > expected)
                    ? (int)((long long)out_size - expected) : 0;

    cudaFuncSetAttribute(hankel_filterbank_kernel,
                         cudaFuncAttributeMaxDynamicSharedMemorySize, SMEM_BYTES);

    int nb = NB_MAIN + (extra > 0 ? 1 : 0);
    hankel_filterbank_kernel<<<nb, THREADS, SMEM_BYTES>>>(x, W, bv, out,
                                                          expected, extra);
}

// round 12
// speedup vs baseline: 1.0451x; 1.0451x over previous
#include <cuda_runtime.h>
#include <cstdint>

#define Bn 16
#define Ln 65536
#define Hn 64
#define Kn 64
#define LOUT (Ln - Hn + 1)              /* 65473 */
#define TILE_M 256
#define NTILES ((LOUT + TILE_M - 1) / TILE_M)   /* 256 */
#define THREADS 256                      /* 8 warps, each M=32 x N=64 */

// ---- dynamic SMEM layout (bytes) ----
#define OFF_S     0          /* 64 floats: S_k */
#define OFF_BV    256        /* 64 floats: b_k */
#define OFF_INV   512        /* 256 floats: 1/(sd+eps) */
#define OFF_MUI   1536       /* 256 floats: mu*inv */
#define OFF_XS    2560       /* 328 floats: tf32-rounded x window */
#define OFF_XS2   3872       /* 320 float2: {xs[i], xs[i+4]} pairs */
#define OFF_W     6432       /* 64 rows x 272B (68 words: 4 mod 32 -> bank-clean) */
#define SMEM_BYTES (OFF_W + 64 * 272)   /* 23840 */

__device__ float2 g_Wp[Kn * 32];   // [n][kk*4+ct] = {W~[n][kk*8+ct], W~[n][kk*8+ct+4]}
__device__ float  g_S[Kn];

__device__ __forceinline__ float tf32r(float v) {
    uint32_t t;
    asm("cvt.rna.tf32.f32 %0, %1;" : "=r"(t) : "f"(v));
    return __uint_as_float(t);
}

__device__ __forceinline__ void mma_tf32(float* c, const uint32_t* a,
                                         uint32_t b0, uint32_t b1) {
    asm volatile(
        "mma.sync.aligned.m16n8k8.row.col.f32.tf32.tf32.f32 "
        "{%0,%1,%2,%3}, {%4,%5,%6,%7}, {%8,%9}, {%0,%1,%2,%3};"
        : "+f"(c[0]), "+f"(c[1]), "+f"(c[2]), "+f"(c[3])
        : "r"(a[0]), "r"(a[1]), "r"(a[2]), "r"(a[3]), "r"(b0), "r"(b1));
}

// prep: blocks 0..7 build permuted tf32 W + S_k; block 8 fills tuple tail
__global__ void prep_kernel(const float* __restrict__ W, float* __restrict__ out,
                            long long expected, int extra) {
    if (blockIdx.x == 8) {
        for (int i = threadIdx.x; i < extra; i += blockDim.x)
            out[expected + i] = 63.0f;   // warmup scalar
        return;
    }
    int i = blockIdx.x * blockDim.x + threadIdx.x;   // 0..2047
    int lane = i & 31;
    {
        int n = i >> 5, r = i & 31, kk = r >> 2, ct = r & 3;
        float2 p;
        p.x = tf32r(W[n * Hn + kk * 8 + ct]);
        p.y = tf32r(W[n * Hn + kk * 8 + ct + 4]);
        g_Wp[i] = p;
    }
    {
        int row = i >> 5;   // 0..63, one warp per k-row
        float v = tf32r(W[row * Hn + lane]) + tf32r(W[row * Hn + 32 + lane]);
#pragma unroll
        for (int o = 16; o > 0; o >>= 1)
            v += __shfl_xor_sync(0xFFFFFFFFu, v, o);
        if (lane == 0) g_S[row] = v;
    }
}

__global__ void __launch_bounds__(THREADS, 2)
hankel_filterbank_kernel(const float* __restrict__ x,
                         const float* __restrict__ bv,
                         float* __restrict__ out)
{
    extern __shared__ char sm[];
    const int tid = threadIdx.x;
    const int wid = tid >> 5;
    const int lid = tid & 31;
    const int g   = lid >> 2;     // group id 0..7
    const int ct  = lid & 3;      // thread-in-group
    const int t0  = (blockIdx.x & (NTILES - 1)) * TILE_M;
    const int batch = blockIdx.x >> 8;   // NTILES == 256

    float* xs   = (float*)(sm + OFF_XS);
    float2* xs2 = (float2*)(sm + OFF_XS2);

    // ---- stage + tf32-round x window (zero past end) ----
    const float* xb = x + (size_t)batch * Ln;
#pragma unroll
    for (int i = tid; i < 328; i += THREADS) {
        int gi = t0 + i;
        xs[i] = (gi < Ln) ? tf32r(xb[gi]) : 0.0f;
    }

    // ---- copy permuted tf32 W into 272B rows (bank-clean stride) ----
    {
        const float4* src = (const float4*)g_Wp;
#pragma unroll
        for (int j = tid; j < 1024; j += THREADS) {
            int n = j >> 4, q = j & 15;
            *(float4*)(sm + OFF_W + n * 272 + q * 16) = src[j];
        }
    }
    if (tid < Kn) {
        ((float*)(sm + OFF_S))[tid]  = g_S[tid];
        ((float*)(sm + OFF_BV))[tid] = bv[tid];
    }
    __syncthreads();

    // ---- xs2 pairs; per-row stats (row = tid) ----
#pragma unroll
    for (int i = tid; i < 320; i += THREADS) {
        float2 p;
        p.x = xs[i];
        p.y = xs[i + 4];
        xs2[i] = p;
    }
    {
        float sum = 0.0f, sq = 0.0f;
#pragma unroll
        for (int h = 0; h < Hn; ++h) {
            float v = xs[tid + h];
            sum += v;
            sq = fmaf(v, v, sq);
        }
        float mu  = sum * (1.0f / 64.0f);
        float var = fmaxf(sq - sum * mu, 0.0f) * (1.0f / 63.0f);
        float inv = 1.0f / (sqrtf(var) + 1e-6f);
        ((float*)(sm + OFF_INV))[tid] = inv;
        ((float*)(sm + OFF_MUI))[tid] = mu * inv;
    }
    __syncthreads();

    // ---- A-fragment register cache: sliding window across kk ----
    // aA0(kk)=v[kk], aB0=v[kk+1], aA1=v[kk+2], aB1=v[kk+3]
    const int Rw = wid << 5;   // warp row base within tile
    float2 v[11];
#pragma unroll
    for (int j = 0; j < 11; ++j) v[j] = xs2[Rw + g + ct + 8 * j];

    float c[2][8][4];
#pragma unroll
    for (int mb = 0; mb < 2; ++mb)
#pragma unroll
        for (int nb = 0; nb < 8; ++nb)
#pragma unroll
            for (int r = 0; r < 4; ++r) c[mb][nb][r] = 0.0f;

#pragma unroll
    for (int kk = 0; kk < 8; ++kk) {
        uint32_t a0[4] = { __float_as_uint(v[kk].x),     __float_as_uint(v[kk + 1].x),
                           __float_as_uint(v[kk].y),     __float_as_uint(v[kk + 1].y) };
        uint32_t a1[4] = { __float_as_uint(v[kk + 2].x), __float_as_uint(v[kk + 3].x),
                           __float_as_uint(v[kk + 2].y), __float_as_uint(v[kk + 3].y) };
#pragma unroll
        for (int nb = 0; nb < 8; ++nb) {
            int n = (nb << 3) + g;
            float2 bb = *(const float2*)(sm + OFF_W + n * 272 + (kk * 4 + ct) * 8);
            uint32_t b0 = __float_as_uint(bb.x), b1 = __float_as_uint(bb.y);
            mma_tf32(c[0][nb], a0, b0, b1);
            mma_tf32(c[1][nb], a1, b0, b1);
        }
    }

    // ---- epilogue: direct register -> global streaming stores ----
    // per STG.64: lanes (g,ct) cover 8 rows x 32 contiguous bytes (sector-aligned)
    const float* Ss  = (const float*)(sm + OFF_S);
    const float* bs  = (const float*)(sm + OFF_BV);
    const float* inv = (const float*)(sm + OFF_INV);
    const float* mui = (const float*)(sm + OFF_MUI);
    float* outb = out + (size_t)batch * LOUT * Kn;

#pragma unroll
    for (int mb = 0; mb < 2; ++mb) {
        const int rA = Rw + (mb << 4) + g;
        const float iA = inv[rA],     mA = mui[rA];
        const float iB = inv[rA + 8], mB = mui[rA + 8];
        const int gA = t0 + rA;
        const bool okA = gA < LOUT, okB = (gA + 8) < LOUT;
        float* pA = outb + (size_t)gA * Kn + (ct << 1);
        float* pB = pA + (size_t)8 * Kn;
#pragma unroll
        for (int nb = 0; nb < 8; ++nb) {
            int col = (nb << 3) + (ct << 1);
            float2 S2 = *(const float2*)(Ss + col);
            float2 b2 = *(const float2*)(bs + col);
            float2 yA, yB;
            yA.x = fmaxf(fmaf(c[mb][nb][0], iA, fmaf(-mA, S2.x, b2.x)), 0.0f);
            yA.y = fmaxf(fmaf(c[mb][nb][1], iA, fmaf(-mA, S2.y, b2.y)), 0.0f);
            yB.x = fmaxf(fmaf(c[mb][nb][2], iB, fmaf(-mB, S2.x, b2.x)), 0.0f);
            yB.y = fmaxf(fmaf(c[mb][nb][3], iB, fmaf(-mB, S2.y, b2.y)), 0.0f);
            if (okA) __stcs((float2*)(pA + (nb << 3)), yA);
            if (okB) __stcs((float2*)(pB + (nb << 3)), yB);
        }
    }
}

extern "C" void kernel_launch(void* const* d_in, const int* in_sizes, int n_in,
                              void* d_out, int out_size) {
    const float* x  = (const float*)d_in[0];
    const float* W  = (const float*)d_in[1];
    const float* bv = (const float*)d_in[2];
    float* out = (float*)d_out;

    long long expected = (long long)Bn * LOUT * Kn;
    int extra = ((long long)out_size > expected)
                    ? (int)((long long)out_size - expected) : 0;

    prep_kernel<<<9, 256>>>(W, out, expected, extra);

    cudaFuncSetAttribute(hankel_filterbank_kernel,
                         cudaFuncAttributeMaxDynamicSharedMemorySize, SMEM_BYTES);
    hankel_filterbank_kernel<<<NTILES * Bn, THREADS, SMEM_BYTES>>>(x, bv, out);
}